// round 4
// baseline (speedup 1.0000x reference)
#include <cuda_runtime.h>
#include <cuda_bf16.h>

// EdgeMLP: out = silu( silu( LN( [src|edge] @ W1 + b1 ) ) @ W2 + b2 )
// E=500000, NODE=128, EDGE=64, IN=192, OUT=128, fp32 throughout.
//
// Strategy: weights resident in SMEM (160KB) -> 1 CTA/SM, 256 thr.
// 64-row tiles; per-thread 4x8 micro-tile with packed fma.rn.f32x2
// (column pairs come directly from LDS.128 of the weight row).

static constexpr int NODE_DIM = 128;
static constexpr int EDGE_DIM = 64;
static constexpr int IN_DIM   = 192;
static constexpr int OUT_DIM  = 128;

static constexpr int BR      = 64;    // rows per tile
static constexpr int THREADS = 256;
static constexpr int XSTR    = 193;   // padded X stride (odd -> conflict-free row access)
static constexpr int HSTR    = 129;   // padded H stride

// shared memory layout (float offsets)
static constexpr int OFF_W1  = 0;                       // 192*128
static constexpr int OFF_W2  = OFF_W1 + IN_DIM * OUT_DIM;   // 128*128
static constexpr int OFF_B1  = OFF_W2 + OUT_DIM * OUT_DIM;
static constexpr int OFF_B2  = OFF_B1 + OUT_DIM;
static constexpr int OFF_G   = OFF_B2 + OUT_DIM;
static constexpr int OFF_BT  = OFF_G  + OUT_DIM;
static constexpr int OFF_BUF = OFF_BT + OUT_DIM;        // BR*XSTR floats (X / reused as H)
static constexpr int SMEM_FLOATS = OFF_BUF + BR * XSTR;
static constexpr int SMEM_BYTES  = SMEM_FLOATS * 4;     // 215296 B < 227KB limit

// ---------- packed fp32x2 helpers (sm_100+ PTX) ----------
__device__ __forceinline__ unsigned long long ffma2(unsigned long long a,
                                                    unsigned long long b,
                                                    unsigned long long c) {
    unsigned long long d;
    asm("fma.rn.f32x2 %0, %1, %2, %3;" : "=l"(d) : "l"(a), "l"(b), "l"(c));
    return d;
}
__device__ __forceinline__ unsigned long long dup2(float x) {
    unsigned long long r;
    asm("mov.b64 %0, {%1, %1};" : "=l"(r) : "f"(x));
    return r;
}
__device__ __forceinline__ float2 unpack2(unsigned long long v) {
    float2 f;
    asm("mov.b64 {%0, %1}, %2;" : "=f"(f.x), "=f"(f.y) : "l"(v));
    return f;
}
__device__ __forceinline__ float silu_f(float y) {
    // y * sigmoid(y); fast exp+div, rel err ~2e-6 << 1e-3 tolerance.
    return __fdividef(y, 1.0f + __expf(-y));
}

// ---------- register-tiled GEMM over SMEM operands ----------
// Computes acc[4 rows][4 col-pairs] = sBias (broadcast) + sX[r0..r0+3][0:K] @ sW[0:K][c0..c0+7]
template <int K, int XS>
__device__ __forceinline__ void gemm_tile(const float* __restrict__ sX,
                                          const float* __restrict__ sW,
                                          const float* __restrict__ sB,
                                          int r0, int c0,
                                          unsigned long long acc[4][4]) {
#pragma unroll
    for (int p = 0; p < 4; p++) {
        unsigned long long bp = *(const unsigned long long*)(sB + c0 + 2 * p);
        acc[0][p] = bp; acc[1][p] = bp; acc[2][p] = bp; acc[3][p] = bp;
    }
#pragma unroll 4
    for (int k = 0; k < K; k++) {
        unsigned long long a0 = dup2(sX[(r0 + 0) * XS + k]);
        unsigned long long a1 = dup2(sX[(r0 + 1) * XS + k]);
        unsigned long long a2 = dup2(sX[(r0 + 2) * XS + k]);
        unsigned long long a3 = dup2(sX[(r0 + 3) * XS + k]);
        const ulonglong2 wa = *(const ulonglong2*)(sW + k * OUT_DIM + c0);
        const ulonglong2 wb = *(const ulonglong2*)(sW + k * OUT_DIM + c0 + 4);
        const unsigned long long w0 = wa.x, w1 = wa.y, w2 = wb.x, w3 = wb.y;
        acc[0][0] = ffma2(a0, w0, acc[0][0]);
        acc[0][1] = ffma2(a0, w1, acc[0][1]);
        acc[0][2] = ffma2(a0, w2, acc[0][2]);
        acc[0][3] = ffma2(a0, w3, acc[0][3]);
        acc[1][0] = ffma2(a1, w0, acc[1][0]);
        acc[1][1] = ffma2(a1, w1, acc[1][1]);
        acc[1][2] = ffma2(a1, w2, acc[1][2]);
        acc[1][3] = ffma2(a1, w3, acc[1][3]);
        acc[2][0] = ffma2(a2, w0, acc[2][0]);
        acc[2][1] = ffma2(a2, w1, acc[2][1]);
        acc[2][2] = ffma2(a2, w2, acc[2][2]);
        acc[2][3] = ffma2(a2, w3, acc[2][3]);
        acc[3][0] = ffma2(a3, w0, acc[3][0]);
        acc[3][1] = ffma2(a3, w1, acc[3][1]);
        acc[3][2] = ffma2(a3, w2, acc[3][2]);
        acc[3][3] = ffma2(a3, w3, acc[3][3]);
    }
}

__global__ void __launch_bounds__(THREADS, 1)
edge_mlp_kernel(const float* __restrict__ src, const float* __restrict__ edg,
                const float* __restrict__ W1,  const float* __restrict__ b1,
                const float* __restrict__ gam, const float* __restrict__ bet,
                const float* __restrict__ W2,  const float* __restrict__ b2,
                float* __restrict__ out, int E, int ntiles) {
    extern __shared__ float sm[];
    float* sW1  = sm + OFF_W1;
    float* sW2  = sm + OFF_W2;
    float* sB1  = sm + OFF_B1;
    float* sB2  = sm + OFF_B2;
    float* sG   = sm + OFF_G;
    float* sBt  = sm + OFF_BT;
    float* sBuf = sm + OFF_BUF;   // X (stride XSTR) then reused as H (stride HSTR)

    const int tid = threadIdx.x;

    // One-time weight/bias preload (block-persistent over several tiles).
    for (int i = tid; i < IN_DIM * OUT_DIM; i += THREADS) sW1[i] = W1[i];
    for (int i = tid; i < OUT_DIM * OUT_DIM; i += THREADS) sW2[i] = W2[i];
    if (tid < OUT_DIM) {
        sB1[tid] = b1[tid];
        sB2[tid] = b2[tid];
        sG[tid]  = gam[tid];
        sBt[tid] = bet[tid];
    }

    const int cg = tid & 15;         // column group: cols 8*cg .. 8*cg+7
    const int rg = tid >> 4;         // row group:    rows 4*rg .. 4*rg+3
    const int r0 = rg * 4, c0 = cg * 8;
    const int warp = tid >> 5, lane = tid & 31;

    for (int tile = blockIdx.x; tile < ntiles; tile += gridDim.x) {
        const int rowbase = tile * BR;

        __syncthreads();   // buf free from previous iteration (also orders preload on iter 0)

        // ---- stage X tile: concat(src, edge), zero-padded past E ----
        for (int i = tid; i < BR * IN_DIM; i += THREADS) {
            int r = i / IN_DIM;
            int c = i - r * IN_DIM;
            int row = rowbase + r;
            float v = 0.0f;
            if (row < E)
                v = (c < NODE_DIM) ? src[(size_t)row * NODE_DIM + c]
                                   : edg[(size_t)row * EDGE_DIM + (c - NODE_DIM)];
            sBuf[r * XSTR + c] = v;
        }
        __syncthreads();

        // ---- GEMM1: H = X @ W1 + b1 ----
        unsigned long long acc[4][4];
        gemm_tile<IN_DIM, XSTR>(sBuf, sW1, sB1, r0, c0, acc);
        __syncthreads();   // X no longer needed; buf becomes H

#pragma unroll
        for (int i = 0; i < 4; i++)
#pragma unroll
            for (int p = 0; p < 4; p++) {
                float2 v = unpack2(acc[i][p]);
                sBuf[(r0 + i) * HSTR + c0 + 2 * p]     = v.x;
                sBuf[(r0 + i) * HSTR + c0 + 2 * p + 1] = v.y;
            }
        __syncthreads();

        // ---- LayerNorm + SiLU, warp = 8 rows, lane owns 4 columns ----
        for (int rr = 0; rr < 8; rr++) {
            const int r = warp * 8 + rr;
            float v0 = sBuf[r * HSTR + lane];
            float v1 = sBuf[r * HSTR + lane + 32];
            float v2 = sBuf[r * HSTR + lane + 64];
            float v3 = sBuf[r * HSTR + lane + 96];
            float s = v0 + v1 + v2 + v3;
#pragma unroll
            for (int o = 16; o > 0; o >>= 1) s += __shfl_xor_sync(0xffffffffu, s, o);
            const float mu = s * (1.0f / 128.0f);
            float d0 = v0 - mu, d1 = v1 - mu, d2 = v2 - mu, d3 = v3 - mu;
            float q = d0 * d0 + d1 * d1 + d2 * d2 + d3 * d3;
#pragma unroll
            for (int o = 16; o > 0; o >>= 1) q += __shfl_xor_sync(0xffffffffu, q, o);
            const float rs = rsqrtf(q * (1.0f / 128.0f) + 1e-5f);
            float y0 = d0 * rs * sG[lane]      + sBt[lane];
            float y1 = d1 * rs * sG[lane + 32] + sBt[lane + 32];
            float y2 = d2 * rs * sG[lane + 64] + sBt[lane + 64];
            float y3 = d3 * rs * sG[lane + 96] + sBt[lane + 96];
            sBuf[r * HSTR + lane]      = silu_f(y0);
            sBuf[r * HSTR + lane + 32] = silu_f(y1);
            sBuf[r * HSTR + lane + 64] = silu_f(y2);
            sBuf[r * HSTR + lane + 96] = silu_f(y3);
        }
        __syncthreads();

        // ---- GEMM2: Z = H @ W2 + b2 ----
        gemm_tile<OUT_DIM, HSTR>(sBuf, sW2, sB2, r0, c0, acc);

        // ---- epilogue: SiLU + vectorized store ----
#pragma unroll
        for (int i = 0; i < 4; i++) {
            const int row = rowbase + r0 + i;
            if (row < E) {
                float o[8];
#pragma unroll
                for (int p = 0; p < 4; p++) {
                    float2 v = unpack2(acc[i][p]);
                    o[2 * p]     = silu_f(v.x);
                    o[2 * p + 1] = silu_f(v.y);
                }
                float4* dst = (float4*)(out + (size_t)row * OUT_DIM + c0);
                dst[0] = make_float4(o[0], o[1], o[2], o[3]);
                dst[1] = make_float4(o[4], o[5], o[6], o[7]);
            }
        }
        // next-iteration top __syncthreads protects sBuf before refill
    }
}

extern "C" void kernel_launch(void* const* d_in, const int* in_sizes, int n_in,
                              void* d_out, int out_size) {
    const float* src = (const float*)d_in[0];
    const float* edg = (const float*)d_in[1];
    const float* W1  = (const float*)d_in[2];
    const float* b1  = (const float*)d_in[3];
    const float* gam = (const float*)d_in[4];
    const float* bet = (const float*)d_in[5];
    const float* W2  = (const float*)d_in[6];
    const float* b2  = (const float*)d_in[7];
    float* out = (float*)d_out;

    const int E = in_sizes[0] / NODE_DIM;
    const int ntiles = (E + BR - 1) / BR;

    cudaFuncSetAttribute(edge_mlp_kernel,
                         cudaFuncAttributeMaxDynamicSharedMemorySize, SMEM_BYTES);

    // grid = 8*148: equal-share grid-stride; wave-quantization error <= ~3%
    // on either 148-SM (B300) or 152-SM (GB300) parts.
    const int grid = 1184;
    edge_mlp_kernel<<<grid, THREADS, SMEM_BYTES>>>(src, edg, W1, b1, gam, bet,
                                                   W2, b2, out, E, ntiles);
}

// round 5
// speedup vs baseline: 2.5168x; 2.5168x over previous
#include <cuda_runtime.h>
#include <cuda_bf16.h>

// EdgeMLP: out = silu( silu( LN( [src|edge] @ W1 + b1 ) ) @ W2 + b2 )
// E=500000, NODE=128, EDGE=64, IN=192, OUT=128, fp32.
//
// v2: 128-row tiles, 8x8 per-thread micro-tile, k-blocked-by-4 LDS.128
// operand loads, packed fma.rn.f32x2 -> fma-pipe bound (~1 B/FMA smem).

static constexpr int NODE_DIM = 128;
static constexpr int EDGE_DIM = 64;
static constexpr int OUT_DIM  = 128;

static constexpr int BR      = 128;   // rows per tile
static constexpr int THREADS = 256;

// shared memory layout (float offsets)
static constexpr int OFF_W1  = 0;                          // 192*128
static constexpr int OFF_W2  = OFF_W1 + 192 * OUT_DIM;     // 128*128
static constexpr int OFF_B1  = OFF_W2 + OUT_DIM * OUT_DIM;
static constexpr int OFF_B2  = OFF_B1 + OUT_DIM;
static constexpr int OFF_G   = OFF_B2 + OUT_DIM;
static constexpr int OFF_BT  = OFF_G  + OUT_DIM;
static constexpr int OFF_BUF = OFF_BT + OUT_DIM;           // 128*128 floats (X chunk / H)
static constexpr int SMEM_FLOATS = OFF_BUF + BR * 128;
static constexpr int SMEM_BYTES  = SMEM_FLOATS * 4;        // 231424 B <= 232448 limit

typedef unsigned long long ull;

// ---------- packed fp32x2 helpers ----------
__device__ __forceinline__ ull ffma2(ull a, ull b, ull c) {
    ull d;
    asm("fma.rn.f32x2 %0, %1, %2, %3;" : "=l"(d) : "l"(a), "l"(b), "l"(c));
    return d;
}
__device__ __forceinline__ ull dup2(float x) {
    ull r;
    asm("mov.b64 %0, {%1, %1};" : "=l"(r) : "f"(x));
    return r;
}
__device__ __forceinline__ float2 unpack2(ull v) {
    float2 f;
    asm("mov.b64 {%0, %1}, %2;" : "=f"(f.x), "=f"(f.y) : "l"(v));
    return f;
}
__device__ __forceinline__ float silu_f(float y) {
    return __fdividef(y, 1.0f + __expf(-y));   // rel err ~2e-6 << 1e-3
}

// ---------- bias broadcast into accumulators ----------
__device__ __forceinline__ void acc_init(const float* __restrict__ sB, int c0,
                                         ull acc[8][4]) {
#pragma unroll
    for (int p = 0; p < 4; p++) {
        ull bp = *(const ull*)(sB + c0 + 2 * p);
#pragma unroll
        for (int i = 0; i < 8; i++) acc[i][p] = bp;
    }
}

// ---------- register-tiled GEMM accumulate over SMEM operands ----------
// acc[8 rows][4 col-pairs] += sA[r0..r0+7][0:KC] @ sW[0:KC][c0..c0+7]
// AS = row stride of sA (floats, multiple of 4).
template <int KC, int AS>
__device__ __forceinline__ void gemm_acc(const float* __restrict__ sA,
                                         const float* __restrict__ sW,
                                         int r0, int c0, ull acc[8][4]) {
#pragma unroll 1
    for (int kb = 0; kb < KC / 4; kb++) {
        float4 xa[8];
#pragma unroll
        for (int i = 0; i < 8; i++)
            xa[i] = *(const float4*)(sA + (r0 + i) * AS + kb * 4);
#pragma unroll
        for (int kk = 0; kk < 4; kk++) {
            const int k = kb * 4 + kk;
            const ulonglong2 wa = *(const ulonglong2*)(sW + k * OUT_DIM + c0);
            const ulonglong2 wb = *(const ulonglong2*)(sW + k * OUT_DIM + c0 + 4);
            const ull w0 = wa.x, w1 = wa.y, w2 = wb.x, w3 = wb.y;
#pragma unroll
            for (int i = 0; i < 8; i++) {
                const float xs = (kk == 0) ? xa[i].x
                               : (kk == 1) ? xa[i].y
                               : (kk == 2) ? xa[i].z : xa[i].w;
                const ull a = dup2(xs);
                acc[i][0] = ffma2(a, w0, acc[i][0]);
                acc[i][1] = ffma2(a, w1, acc[i][1]);
                acc[i][2] = ffma2(a, w2, acc[i][2]);
                acc[i][3] = ffma2(a, w3, acc[i][3]);
            }
        }
    }
}

__global__ void __launch_bounds__(THREADS, 1)
edge_mlp_kernel(const float* __restrict__ src, const float* __restrict__ edg,
                const float* __restrict__ W1,  const float* __restrict__ b1,
                const float* __restrict__ gam, const float* __restrict__ bet,
                const float* __restrict__ W2,  const float* __restrict__ b2,
                float* __restrict__ out, int E, int ntiles) {
    extern __shared__ float sm[];
    float* sW1  = sm + OFF_W1;
    float* sW2  = sm + OFF_W2;
    float* sB1  = sm + OFF_B1;
    float* sB2  = sm + OFF_B2;
    float* sG   = sm + OFF_G;
    float* sBt  = sm + OFF_BT;
    float* sBuf = sm + OFF_BUF;

    const int tid = threadIdx.x;

    // One-time weight/bias preload (persistent CTA).
    for (int i = tid; i < 192 * OUT_DIM; i += THREADS) sW1[i] = W1[i];
    for (int i = tid; i < OUT_DIM * OUT_DIM; i += THREADS) sW2[i] = W2[i];
    if (tid < OUT_DIM) {
        sB1[tid] = b1[tid];
        sB2[tid] = b2[tid];
        sG[tid]  = gam[tid];
        sBt[tid] = bet[tid];
    }

    const int cg = tid & 15;          // cols 8*cg .. 8*cg+7
    const int rg = tid >> 4;          // rows 8*rg .. 8*rg+7
    const int r0 = rg * 8, c0 = cg * 8;
    const int warp = tid >> 5, lane = tid & 31;

    for (int tile = blockIdx.x; tile < ntiles; tile += gridDim.x) {
        const int rowbase = tile * BR;
        const bool full = (rowbase + BR <= E);

        __syncthreads();   // sBuf free (covers preload on iter 0 too)

        // ---- stage src chunk: 128 x 128, contiguous float4 copy ----
        {
            float4* d4 = (float4*)sBuf;
            const int n4 = BR * NODE_DIM / 4;
            if (full) {
                const float4* s4 = (const float4*)(src + (size_t)rowbase * NODE_DIM);
#pragma unroll
                for (int j = 0; j < n4 / THREADS; j++) d4[tid + j * THREADS] = s4[tid + j * THREADS];
            } else {
                for (int i = tid; i < n4; i += THREADS) {
                    const int r = i / (NODE_DIM / 4);
                    float4 v = make_float4(0.f, 0.f, 0.f, 0.f);
                    if (rowbase + r < E)
                        v = ((const float4*)(src + (size_t)rowbase * NODE_DIM))[i];
                    d4[i] = v;
                }
            }
        }
        __syncthreads();

        // ---- GEMM1 part A: src @ W1[0:128] + b1 ----
        ull acc[8][4];
        acc_init(sB1, c0, acc);
        gemm_acc<NODE_DIM, 128>(sBuf, sW1, r0, c0, acc);
        __syncthreads();   // done reading src chunk

        // ---- stage edge chunk: 128 x 64, contiguous float4 copy ----
        {
            float4* d4 = (float4*)sBuf;
            const int n4 = BR * EDGE_DIM / 4;
            if (full) {
                const float4* s4 = (const float4*)(edg + (size_t)rowbase * EDGE_DIM);
#pragma unroll
                for (int j = 0; j < n4 / THREADS; j++) d4[tid + j * THREADS] = s4[tid + j * THREADS];
            } else {
                for (int i = tid; i < n4; i += THREADS) {
                    const int r = i / (EDGE_DIM / 4);
                    float4 v = make_float4(0.f, 0.f, 0.f, 0.f);
                    if (rowbase + r < E)
                        v = ((const float4*)(edg + (size_t)rowbase * EDGE_DIM))[i];
                    d4[i] = v;
                }
            }
        }
        __syncthreads();

        // ---- GEMM1 part B: edge @ W1[128:192] ----
        gemm_acc<EDGE_DIM, 64>(sBuf, sW1 + NODE_DIM * OUT_DIM, r0, c0, acc);
        __syncthreads();   // done reading edge chunk; sBuf becomes H

        // ---- spill H (stride 128) ----
#pragma unroll
        for (int i = 0; i < 8; i++) {
            ull* dst = (ull*)(sBuf + (r0 + i) * 128 + c0);
            dst[0] = acc[i][0];
            dst[1] = acc[i][1];
            dst[2] = acc[i][2];
            dst[3] = acc[i][3];
        }
        __syncthreads();

        // ---- LayerNorm + SiLU in place: warp = 16 rows ----
        for (int rr = 0; rr < 16; rr++) {
            const int r = warp * 16 + rr;
            float v0 = sBuf[r * 128 + lane];
            float v1 = sBuf[r * 128 + lane + 32];
            float v2 = sBuf[r * 128 + lane + 64];
            float v3 = sBuf[r * 128 + lane + 96];
            float s = v0 + v1 + v2 + v3;
#pragma unroll
            for (int o = 16; o > 0; o >>= 1) s += __shfl_xor_sync(0xffffffffu, s, o);
            const float mu = s * (1.0f / 128.0f);
            const float d0 = v0 - mu, d1 = v1 - mu, d2 = v2 - mu, d3 = v3 - mu;
            float q = d0 * d0 + d1 * d1 + d2 * d2 + d3 * d3;
#pragma unroll
            for (int o = 16; o > 0; o >>= 1) q += __shfl_xor_sync(0xffffffffu, q, o);
            const float rs = rsqrtf(q * (1.0f / 128.0f) + 1e-5f);
            sBuf[r * 128 + lane]      = silu_f(d0 * rs * sG[lane]      + sBt[lane]);
            sBuf[r * 128 + lane + 32] = silu_f(d1 * rs * sG[lane + 32] + sBt[lane + 32]);
            sBuf[r * 128 + lane + 64] = silu_f(d2 * rs * sG[lane + 64] + sBt[lane + 64]);
            sBuf[r * 128 + lane + 96] = silu_f(d3 * rs * sG[lane + 96] + sBt[lane + 96]);
        }
        __syncthreads();

        // ---- GEMM2: H @ W2 + b2 ----
        acc_init(sB2, c0, acc);
        gemm_acc<OUT_DIM, 128>(sBuf, sW2, r0, c0, acc);

        // ---- epilogue: SiLU + vectorized store ----
#pragma unroll
        for (int i = 0; i < 8; i++) {
            const int row = rowbase + r0 + i;
            if (row < E) {
                float o[8];
#pragma unroll
                for (int p = 0; p < 4; p++) {
                    float2 v = unpack2(acc[i][p]);
                    o[2 * p]     = silu_f(v.x);
                    o[2 * p + 1] = silu_f(v.y);
                }
                float4* dst = (float4*)(out + (size_t)row * OUT_DIM + c0);
                dst[0] = make_float4(o[0], o[1], o[2], o[3]);
                dst[1] = make_float4(o[4], o[5], o[6], o[7]);
            }
        }
        // top-of-loop sync protects sBuf before next restage
    }
}

extern "C" void kernel_launch(void* const* d_in, const int* in_sizes, int n_in,
                              void* d_out, int out_size) {
    const float* src = (const float*)d_in[0];
    const float* edg = (const float*)d_in[1];
    const float* W1  = (const float*)d_in[2];
    const float* b1  = (const float*)d_in[3];
    const float* gam = (const float*)d_in[4];
    const float* bet = (const float*)d_in[5];
    const float* W2  = (const float*)d_in[6];
    const float* b2  = (const float*)d_in[7];
    float* out = (float*)d_out;

    const int E = in_sizes[0] / NODE_DIM;
    const int ntiles = (E + BR - 1) / BR;

    cudaFuncSetAttribute(edge_mlp_kernel,
                         cudaFuncAttributeMaxDynamicSharedMemorySize, SMEM_BYTES);

    int nsm = 148;
    if (cudaDeviceGetAttribute(&nsm, cudaDevAttrMultiProcessorCount, 0) != cudaSuccess
        || nsm <= 0)
        nsm = 148;
    int grid = nsm < ntiles ? nsm : ntiles;

    edge_mlp_kernel<<<grid, THREADS, SMEM_BYTES>>>(src, edg, W1, b1, gam, bet,
                                                   W2, b2, out, E, ntiles);
}